// round 15
// baseline (speedup 1.0000x reference)
#include <cuda_runtime.h>
#include <cstdint>

// Problem constants
#define BDIM   128
#define TD     32
#define NT     4      // tokens from x
#define NTOK   5      // +1 learnable
#define NHEAD  8
#define HD     4
#define DEEP   2

// 0.5 * log2(e)  (scale = HD^-0.5 = 0.5, folded with base-2 softmax)
#define SC2 0.7213475204444817f
#define L2E 1.4426950408889634f

typedef unsigned long long u64;

static __device__ __forceinline__ u64 pk2(float lo, float hi) {
    u64 r;
    asm("mov.b64 %0, {%1, %2};" : "=l"(r) : "r"(__float_as_uint(lo)), "r"(__float_as_uint(hi)));
    return r;
}
static __device__ __forceinline__ void up2(u64 v, float& lo, float& hi) {
    unsigned a, b;
    asm("mov.b64 {%0, %1}, %2;" : "=r"(a), "=r"(b) : "l"(v));
    lo = __uint_as_float(a);
    hi = __uint_as_float(b);
}
// packed dual FP32 FMA (Blackwell f32x2 pipe — 2x scalar FFMA throughput)
static __device__ __forceinline__ u64 f2fma(u64 a, u64 b, u64 c) {
    u64 d;
    asm("fma.rn.f32x2 %0, %1, %2, %3;" : "=l"(d) : "l"(a), "l"(b), "l"(c));
    return d;
}
static __device__ __forceinline__ float ex2f(float x) {
    float r;
    asm("ex2.approx.ftz.f32 %0, %1;" : "=f"(r) : "f"(x));
    return r;
}
static __device__ __forceinline__ float rcpf(float x) {
    float r;
    asm("rcp.approx.ftz.f32 %0, %1;" : "=f"(r) : "f"(x));
    return r;
}

__global__ __launch_bounds__(256) void nnvit_kernel(
    const float* __restrict__ x,      // [B,128]
    const float* __restrict__ token,  // [32]
    const float* __restrict__ qkvw,   // [2,96,32]
    const float* __restrict__ qkvb,   // [2,96]
    const float* __restrict__ projw,  // [2,32,32]
    const float* __restrict__ projb,  // [2,32]
    const float* __restrict__ pbias,  // [2,8,5,5]
    float* __restrict__ out,          // [B,32]
    int B)
{
    // ---- staged weights, transposed for conflict-free per-lane reads ----
    __shared__ float sWq[2][32][32];  // [l][c][j] = qkv_w[l][j][c]       (q rows 0..31)
    __shared__ float sWk[2][32][32];  // [l][c][j] = qkv_w[l][32+j][c]
    __shared__ float sWv[2][32][32];  // [l][c][j] = qkv_w[l][64+j][c]
    __shared__ float sPw[2][32][32];  // [l][c][j] = proj_w[l][j][c]
    __shared__ float sB[2][8][25];    // pos_bias * log2(e)
    __shared__ float sQKV0[96];       // layer-0 qkv of the constant class token (bias incl.)

    const int tid = threadIdx.x;

    for (int idx = tid; idx < 2 * 96 * 32; idx += 256) {
        int l = idx / 3072;
        int r = idx - l * 3072;
        int row = r >> 5;      // 0..95
        int c   = r & 31;
        float w = qkvw[idx];
        int which = row >> 5;
        int j = row & 31;
        if (which == 0)      sWq[l][c][j] = w;
        else if (which == 1) sWk[l][c][j] = w;
        else                 sWv[l][c][j] = w;
    }
    for (int idx = tid; idx < 2 * 32 * 32; idx += 256) {
        int l = idx >> 10;
        int r = idx & 1023;
        sPw[l][r & 31][r >> 5] = projw[idx];
    }
    for (int idx = tid; idx < 2 * 8 * 25; idx += 256) {
        (&sB[0][0][0])[idx] = pbias[idx] * L2E;
    }
    // layer-0 qkv for token 0 (row-independent)
    if (tid < 96) {
        float s = qkvb[tid];
        const float* wrow = qkvw + tid * 32;
        #pragma unroll
        for (int c = 0; c < 32; c++) s = fmaf(token[c], wrow[c], s);
        sQKV0[tid] = s;
    }
    __syncthreads();

    const int lane = tid & 31;
    const int wid  = tid >> 5;
    const int gwarp  = blockIdx.x * 8 + wid;
    const int nwarps = gridDim.x * 8;
    const unsigned FULL = 0xffffffffu;

    // per-lane bias registers
    const float bq0 = qkvb[lane],      bk0 = qkvb[32 + lane],  bv0 = qkvb[64 + lane];
    const float bq1 = qkvb[96 + lane], bk1 = qkvb[128 + lane], bv1 = qkvb[160 + lane];
    const float pb0 = projb[lane],     pb1 = projb[32 + lane];
    const float tokj = token[lane];
    const float q00 = sQKV0[lane], k00 = sQKV0[32 + lane], v00 = sQKV0[64 + lane];
    const float* b0row = &sB[0][lane >> 2][0];
    const float* b1row = &sB[1][lane >> 2][0];

    for (int row = gwarp; row < B; row += nwarps) {
        const float* xr = x + (size_t)row * BDIM;
        float y0 = tokj;
        float y1 = xr[lane];
        float y2 = xr[32 + lane];
        float y3 = xr[64 + lane];
        float y4 = xr[96 + lane];

        // ================= LAYER 0 =================
        // qkv for tokens 1..4 (token 0 precomputed). Packed token pairs (1,2),(3,4).
        u64 qA = pk2(bq0, bq0), qB = qA;
        u64 kA = pk2(bk0, bk0), kB = kA;
        u64 vA = pk2(bv0, bv0), vB = vA;
        #pragma unroll 8
        for (int c = 0; c < 32; c++) {
            float a1 = __shfl_sync(FULL, y1, c);
            float a2 = __shfl_sync(FULL, y2, c);
            float a3 = __shfl_sync(FULL, y3, c);
            float a4 = __shfl_sync(FULL, y4, c);
            u64 yA = pk2(a1, a2), yB = pk2(a3, a4);
            float wq = sWq[0][c][lane], wk = sWk[0][c][lane], wv = sWv[0][c][lane];
            u64 wq2 = pk2(wq, wq), wk2 = pk2(wk, wk), wv2 = pk2(wv, wv);
            qA = f2fma(yA, wq2, qA); qB = f2fma(yB, wq2, qB);
            kA = f2fma(yA, wk2, kA); kB = f2fma(yB, wk2, kB);
            vA = f2fma(yA, wv2, vA); vB = f2fma(yB, wv2, vB);
        }
        float q[5], k[5], v[5];
        q[0] = q00; k[0] = k00; v[0] = v00;
        up2(qA, q[1], q[2]); up2(qB, q[3], q[4]);
        up2(kA, k[1], k[2]); up2(kB, k[3], k[4]);
        up2(vA, v[1], v[2]); up2(vB, v[3], v[4]);

        // full 5x5 attention; lane owns (h = lane>>2, d = lane&3)
        float o[5];
        #pragma unroll
        for (int n = 0; n < 5; n++) {
            float p[5];
            #pragma unroll
            for (int m = 0; m < 5; m++) {
                float t = q[n] * k[m];
                t += __shfl_xor_sync(FULL, t, 1);   // reduce over head_dim (quad)
                t += __shfl_xor_sync(FULL, t, 2);
                p[m] = fmaf(t, SC2, b0row[n * 5 + m]);   // log2-domain logits
            }
            float mx = fmaxf(fmaxf(fmaxf(p[0], p[1]), fmaxf(p[2], p[3])), p[4]);
            float e0 = ex2f(p[0] - mx), e1 = ex2f(p[1] - mx), e2 = ex2f(p[2] - mx);
            float e3 = ex2f(p[3] - mx), e4 = ex2f(p[4] - mx);
            float s = ((e0 + e1) + (e2 + e3)) + e4;
            float acc = e0 * v[0];
            acc = fmaf(e1, v[1], acc);
            acc = fmaf(e2, v[2], acc);
            acc = fmaf(e3, v[3], acc);
            acc = fmaf(e4, v[4], acc);
            o[n] = acc * rcpf(s);
        }

        // proj + residual (packed token pairs (0,1),(2,3); token 4 scalar)
        u64 zA = pk2(pb0, pb0), zB = zA;
        float z4 = pb0;
        #pragma unroll 8
        for (int c = 0; c < 32; c++) {
            float w = sPw[0][c][lane];
            u64 w2 = pk2(w, w);
            float ob0 = __shfl_sync(FULL, o[0], c);
            float ob1 = __shfl_sync(FULL, o[1], c);
            float ob2 = __shfl_sync(FULL, o[2], c);
            float ob3 = __shfl_sync(FULL, o[3], c);
            float ob4 = __shfl_sync(FULL, o[4], c);
            zA = f2fma(pk2(ob0, ob1), w2, zA);
            zB = f2fma(pk2(ob2, ob3), w2, zB);
            z4 = fmaf(ob4, w, z4);
        }
        {
            float z0, z1, z2, z3;
            up2(zA, z0, z1); up2(zB, z2, z3);
            y0 += z0; y1 += z1; y2 += z2; y3 += z3; y4 += z4;
        }

        // ================= LAYER 1 (pruned: only token 0 reaches the output) =================
        // need q only for token 0; k,v for all 5 tokens. Pairs (0,1),(2,3); token 4 scalar.
        float q0 = bq1;
        u64 kA1 = pk2(bk1, bk1), kB1 = kA1;
        u64 vA1 = pk2(bv1, bv1), vB1 = vA1;
        float k4 = bk1, v4 = bv1;
        #pragma unroll 8
        for (int c = 0; c < 32; c++) {
            float a0 = __shfl_sync(FULL, y0, c);
            float a1 = __shfl_sync(FULL, y1, c);
            float a2 = __shfl_sync(FULL, y2, c);
            float a3 = __shfl_sync(FULL, y3, c);
            float a4 = __shfl_sync(FULL, y4, c);
            u64 yA = pk2(a0, a1), yB = pk2(a2, a3);
            float wq = sWq[1][c][lane], wk = sWk[1][c][lane], wv = sWv[1][c][lane];
            u64 wk2 = pk2(wk, wk), wv2 = pk2(wv, wv);
            kA1 = f2fma(yA, wk2, kA1); kB1 = f2fma(yB, wk2, kB1); k4 = fmaf(a4, wk, k4);
            vA1 = f2fma(yA, wv2, vA1); vB1 = f2fma(yB, wv2, vB1); v4 = fmaf(a4, wv, v4);
            q0 = fmaf(a0, wq, q0);
        }
        float kk[5], vv[5];
        up2(kA1, kk[0], kk[1]); up2(kB1, kk[2], kk[3]); kk[4] = k4;
        up2(vA1, vv[0], vv[1]); up2(vB1, vv[2], vv[3]); vv[4] = v4;

        // attention row n=0 only
        float p[5];
        #pragma unroll
        for (int m = 0; m < 5; m++) {
            float t = q0 * kk[m];
            t += __shfl_xor_sync(FULL, t, 1);
            t += __shfl_xor_sync(FULL, t, 2);
            p[m] = fmaf(t, SC2, b1row[m]);
        }
        float mx = fmaxf(fmaxf(fmaxf(p[0], p[1]), fmaxf(p[2], p[3])), p[4]);
        float e0 = ex2f(p[0] - mx), e1 = ex2f(p[1] - mx), e2 = ex2f(p[2] - mx);
        float e3 = ex2f(p[3] - mx), e4 = ex2f(p[4] - mx);
        float s = ((e0 + e1) + (e2 + e3)) + e4;
        float acc = e0 * vv[0];
        acc = fmaf(e1, vv[1], acc);
        acc = fmaf(e2, vv[2], acc);
        acc = fmaf(e3, vv[3], acc);
        acc = fmaf(e4, vv[4], acc);
        float o0 = acc * rcpf(s);

        // proj for token 0 only + residual, then store
        float z = pb1;
        #pragma unroll 8
        for (int c = 0; c < 32; c++) {
            float ob = __shfl_sync(FULL, o0, c);
            z = fmaf(ob, sPw[1][c][lane], z);
        }
        out[(size_t)row * TD + lane] = y0 + z;
    }
}

extern "C" void kernel_launch(void* const* d_in, const int* in_sizes, int n_in,
                              void* d_out, int out_size)
{
    const float* x     = (const float*)d_in[0];
    const float* token = (const float*)d_in[1];
    const float* qkvw  = (const float*)d_in[2];
    const float* qkvb  = (const float*)d_in[3];
    const float* projw = (const float*)d_in[4];
    const float* projb = (const float*)d_in[5];
    const float* pbias = (const float*)d_in[6];
    float* out = (float*)d_out;

    int B = in_sizes[0] / BDIM;

    // 8 warps/CTA, warp-per-row with grid-stride; ~16 rows per warp at B=262144
    int grid = (B + 8 * 16 - 1) / (8 * 16);
    if (grid < 1) grid = 1;
    if (grid > 16384) grid = 16384;

    nnvit_kernel<<<grid, 256>>>(x, token, qkvw, qkvb, projw, projb, pbias, out, B);
}

// round 16
// speedup vs baseline: 1.0021x; 1.0021x over previous
#include <cuda_runtime.h>
#include <cstdint>

// Problem constants
#define BDIM   128
#define TD     32
#define NT     4      // tokens from x
#define NTOK   5      // +1 learnable
#define NHEAD  8
#define HD     4
#define DEEP   2

// 0.5 * log2(e)  (scale = HD^-0.5 = 0.5, folded with base-2 softmax)
#define SC2 0.7213475204444817f
#define L2E 1.4426950408889634f

typedef unsigned long long u64;

static __device__ __forceinline__ u64 pk2(float lo, float hi) {
    u64 r;
    asm("mov.b64 %0, {%1, %2};" : "=l"(r) : "r"(__float_as_uint(lo)), "r"(__float_as_uint(hi)));
    return r;
}
static __device__ __forceinline__ void up2(u64 v, float& lo, float& hi) {
    unsigned a, b;
    asm("mov.b64 {%0, %1}, %2;" : "=r"(a), "=r"(b) : "l"(v));
    lo = __uint_as_float(a);
    hi = __uint_as_float(b);
}
// packed dual FP32 FMA (Blackwell f32x2 pipe — 2x scalar FFMA throughput)
static __device__ __forceinline__ u64 f2fma(u64 a, u64 b, u64 c) {
    u64 d;
    asm("fma.rn.f32x2 %0, %1, %2, %3;" : "=l"(d) : "l"(a), "l"(b), "l"(c));
    return d;
}
static __device__ __forceinline__ float ex2f(float x) {
    float r;
    asm("ex2.approx.ftz.f32 %0, %1;" : "=f"(r) : "f"(x));
    return r;
}
static __device__ __forceinline__ float rcpf(float x) {
    float r;
    asm("rcp.approx.ftz.f32 %0, %1;" : "=f"(r) : "f"(x));
    return r;
}

__global__ __launch_bounds__(256) void nnvit_kernel(
    const float* __restrict__ x,      // [B,128]
    const float* __restrict__ token,  // [32]
    const float* __restrict__ qkvw,   // [2,96,32]
    const float* __restrict__ qkvb,   // [2,96]
    const float* __restrict__ projw,  // [2,32,32]
    const float* __restrict__ projb,  // [2,32]
    const float* __restrict__ pbias,  // [2,8,5,5]
    float* __restrict__ out,          // [B,32]
    int B)
{
    // ---- staged weights, transposed for conflict-free per-lane reads ----
    __shared__ float sWq[2][32][32];  // [l][c][j] = qkv_w[l][j][c]       (q rows 0..31)
    __shared__ float sWk[2][32][32];  // [l][c][j] = qkv_w[l][32+j][c]
    __shared__ float sWv[2][32][32];  // [l][c][j] = qkv_w[l][64+j][c]
    __shared__ float sPw[2][32][32];  // [l][c][j] = proj_w[l][j][c]
    __shared__ float sB[2][8][25];    // pos_bias * log2(e)
    __shared__ float sQKV0[96];       // layer-0 qkv of the constant class token (bias incl.)

    const int tid = threadIdx.x;

    for (int idx = tid; idx < 2 * 96 * 32; idx += 256) {
        int l = idx / 3072;
        int r = idx - l * 3072;
        int row = r >> 5;      // 0..95
        int c   = r & 31;
        float w = qkvw[idx];
        int which = row >> 5;
        int j = row & 31;
        if (which == 0)      sWq[l][c][j] = w;
        else if (which == 1) sWk[l][c][j] = w;
        else                 sWv[l][c][j] = w;
    }
    for (int idx = tid; idx < 2 * 32 * 32; idx += 256) {
        int l = idx >> 10;
        int r = idx & 1023;
        sPw[l][r & 31][r >> 5] = projw[idx];
    }
    for (int idx = tid; idx < 2 * 8 * 25; idx += 256) {
        (&sB[0][0][0])[idx] = pbias[idx] * L2E;
    }
    // layer-0 qkv for token 0 (row-independent)
    if (tid < 96) {
        float s = qkvb[tid];
        const float* wrow = qkvw + tid * 32;
        #pragma unroll
        for (int c = 0; c < 32; c++) s = fmaf(token[c], wrow[c], s);
        sQKV0[tid] = s;
    }
    __syncthreads();

    const int lane = tid & 31;
    const int wid  = tid >> 5;
    const int gwarp  = blockIdx.x * 8 + wid;
    const int nwarps = gridDim.x * 8;
    const unsigned FULL = 0xffffffffu;

    // per-lane bias registers
    const float bq0 = qkvb[lane],      bk0 = qkvb[32 + lane],  bv0 = qkvb[64 + lane];
    const float bq1 = qkvb[96 + lane], bk1 = qkvb[128 + lane], bv1 = qkvb[160 + lane];
    const float pb0 = projb[lane],     pb1 = projb[32 + lane];
    const float tokj = token[lane];
    const float q00 = sQKV0[lane], k00 = sQKV0[32 + lane], v00 = sQKV0[64 + lane];
    const float* b0row = &sB[0][lane >> 2][0];
    const float* b1row = &sB[1][lane >> 2][0];

    for (int row = gwarp; row < B; row += nwarps) {
        const float* xr = x + (size_t)row * BDIM;
        float y0 = tokj;
        float y1 = xr[lane];
        float y2 = xr[32 + lane];
        float y3 = xr[64 + lane];
        float y4 = xr[96 + lane];

        // ================= LAYER 0 =================
        // qkv for tokens 1..4 (token 0 precomputed). Packed token pairs (1,2),(3,4).
        u64 qA = pk2(bq0, bq0), qB = qA;
        u64 kA = pk2(bk0, bk0), kB = kA;
        u64 vA = pk2(bv0, bv0), vB = vA;
        #pragma unroll 8
        for (int c = 0; c < 32; c++) {
            float a1 = __shfl_sync(FULL, y1, c);
            float a2 = __shfl_sync(FULL, y2, c);
            float a3 = __shfl_sync(FULL, y3, c);
            float a4 = __shfl_sync(FULL, y4, c);
            u64 yA = pk2(a1, a2), yB = pk2(a3, a4);
            float wq = sWq[0][c][lane], wk = sWk[0][c][lane], wv = sWv[0][c][lane];
            u64 wq2 = pk2(wq, wq), wk2 = pk2(wk, wk), wv2 = pk2(wv, wv);
            qA = f2fma(yA, wq2, qA); qB = f2fma(yB, wq2, qB);
            kA = f2fma(yA, wk2, kA); kB = f2fma(yB, wk2, kB);
            vA = f2fma(yA, wv2, vA); vB = f2fma(yB, wv2, vB);
        }
        float q[5], k[5], v[5];
        q[0] = q00; k[0] = k00; v[0] = v00;
        up2(qA, q[1], q[2]); up2(qB, q[3], q[4]);
        up2(kA, k[1], k[2]); up2(kB, k[3], k[4]);
        up2(vA, v[1], v[2]); up2(vB, v[3], v[4]);

        // full 5x5 attention; lane owns (h = lane>>2, d = lane&3)
        float o[5];
        #pragma unroll
        for (int n = 0; n < 5; n++) {
            float p[5];
            #pragma unroll
            for (int m = 0; m < 5; m++) {
                float t = q[n] * k[m];
                t += __shfl_xor_sync(FULL, t, 1);   // reduce over head_dim (quad)
                t += __shfl_xor_sync(FULL, t, 2);
                p[m] = fmaf(t, SC2, b0row[n * 5 + m]);   // log2-domain logits
            }
            float mx = fmaxf(fmaxf(fmaxf(p[0], p[1]), fmaxf(p[2], p[3])), p[4]);
            float e0 = ex2f(p[0] - mx), e1 = ex2f(p[1] - mx), e2 = ex2f(p[2] - mx);
            float e3 = ex2f(p[3] - mx), e4 = ex2f(p[4] - mx);
            float s = ((e0 + e1) + (e2 + e3)) + e4;
            float acc = e0 * v[0];
            acc = fmaf(e1, v[1], acc);
            acc = fmaf(e2, v[2], acc);
            acc = fmaf(e3, v[3], acc);
            acc = fmaf(e4, v[4], acc);
            o[n] = acc * rcpf(s);
        }

        // proj + residual (packed token pairs (0,1),(2,3); token 4 scalar)
        u64 zA = pk2(pb0, pb0), zB = zA;
        float z4 = pb0;
        #pragma unroll 8
        for (int c = 0; c < 32; c++) {
            float w = sPw[0][c][lane];
            u64 w2 = pk2(w, w);
            float ob0 = __shfl_sync(FULL, o[0], c);
            float ob1 = __shfl_sync(FULL, o[1], c);
            float ob2 = __shfl_sync(FULL, o[2], c);
            float ob3 = __shfl_sync(FULL, o[3], c);
            float ob4 = __shfl_sync(FULL, o[4], c);
            zA = f2fma(pk2(ob0, ob1), w2, zA);
            zB = f2fma(pk2(ob2, ob3), w2, zB);
            z4 = fmaf(ob4, w, z4);
        }
        {
            float z0, z1, z2, z3;
            up2(zA, z0, z1); up2(zB, z2, z3);
            y0 += z0; y1 += z1; y2 += z2; y3 += z3; y4 += z4;
        }

        // ================= LAYER 1 (pruned: only token 0 reaches the output) =================
        // need q only for token 0; k,v for all 5 tokens. Pairs (0,1),(2,3); token 4 scalar.
        float q0 = bq1;
        u64 kA1 = pk2(bk1, bk1), kB1 = kA1;
        u64 vA1 = pk2(bv1, bv1), vB1 = vA1;
        float k4 = bk1, v4 = bv1;
        #pragma unroll 8
        for (int c = 0; c < 32; c++) {
            float a0 = __shfl_sync(FULL, y0, c);
            float a1 = __shfl_sync(FULL, y1, c);
            float a2 = __shfl_sync(FULL, y2, c);
            float a3 = __shfl_sync(FULL, y3, c);
            float a4 = __shfl_sync(FULL, y4, c);
            u64 yA = pk2(a0, a1), yB = pk2(a2, a3);
            float wq = sWq[1][c][lane], wk = sWk[1][c][lane], wv = sWv[1][c][lane];
            u64 wk2 = pk2(wk, wk), wv2 = pk2(wv, wv);
            kA1 = f2fma(yA, wk2, kA1); kB1 = f2fma(yB, wk2, kB1); k4 = fmaf(a4, wk, k4);
            vA1 = f2fma(yA, wv2, vA1); vB1 = f2fma(yB, wv2, vB1); v4 = fmaf(a4, wv, v4);
            q0 = fmaf(a0, wq, q0);
        }
        float kk[5], vv[5];
        up2(kA1, kk[0], kk[1]); up2(kB1, kk[2], kk[3]); kk[4] = k4;
        up2(vA1, vv[0], vv[1]); up2(vB1, vv[2], vv[3]); vv[4] = v4;

        // attention row n=0 only
        float p[5];
        #pragma unroll
        for (int m = 0; m < 5; m++) {
            float t = q0 * kk[m];
            t += __shfl_xor_sync(FULL, t, 1);
            t += __shfl_xor_sync(FULL, t, 2);
            p[m] = fmaf(t, SC2, b1row[m]);
        }
        float mx = fmaxf(fmaxf(fmaxf(p[0], p[1]), fmaxf(p[2], p[3])), p[4]);
        float e0 = ex2f(p[0] - mx), e1 = ex2f(p[1] - mx), e2 = ex2f(p[2] - mx);
        float e3 = ex2f(p[3] - mx), e4 = ex2f(p[4] - mx);
        float s = ((e0 + e1) + (e2 + e3)) + e4;
        float acc = e0 * vv[0];
        acc = fmaf(e1, vv[1], acc);
        acc = fmaf(e2, vv[2], acc);
        acc = fmaf(e3, vv[3], acc);
        acc = fmaf(e4, vv[4], acc);
        float o0 = acc * rcpf(s);

        // proj for token 0 only + residual, then store
        float z = pb1;
        #pragma unroll 8
        for (int c = 0; c < 32; c++) {
            float ob = __shfl_sync(FULL, o0, c);
            z = fmaf(ob, sPw[1][c][lane], z);
        }
        out[(size_t)row * TD + lane] = y0 + z;
    }
}

extern "C" void kernel_launch(void* const* d_in, const int* in_sizes, int n_in,
                              void* d_out, int out_size)
{
    const float* x     = (const float*)d_in[0];
    const float* token = (const float*)d_in[1];
    const float* qkvw  = (const float*)d_in[2];
    const float* qkvb  = (const float*)d_in[3];
    const float* projw = (const float*)d_in[4];
    const float* projb = (const float*)d_in[5];
    const float* pbias = (const float*)d_in[6];
    float* out = (float*)d_out;

    int B = in_sizes[0] / BDIM;

    // 8 warps/CTA, warp-per-row with grid-stride; ~16 rows per warp at B=262144
    int grid = (B + 8 * 16 - 1) / (8 * 16);
    if (grid < 1) grid = 1;
    if (grid > 16384) grid = 16384;

    nnvit_kernel<<<grid, 256>>>(x, token, qkvw, qkvb, projw, projb, pbias, out, B);
}